// round 2
// baseline (speedup 1.0000x reference)
#include <cuda_runtime.h>
#include <stdint.h>

#define Bn 8
#define Hn 1024
#define Wn 1024
#define HW (Hn * Wn)
#define Nn (Bn * Hn * Wn)
#define THRESH 1.5f
#define MIN_AREA_C 3

// Scratch in __device__ globals (no runtime allocation allowed).
__device__ int                g_parent[Nn];   // fg: union-find parent; bg: -1
__device__ unsigned long long g_agg[Nn];      // per-root packed (val_bits<<32) | ~within
__device__ int                g_area[Nn];     // per-root pixel count

// ---------------------------------------------------------------------------
// Union-find primitives. Roots always decrease (unions point high -> low via
// atomicMin), so read-only find is safe during the merge phase.
// ---------------------------------------------------------------------------
__device__ __forceinline__ int find_ro(int i) {
    int p;
    while ((p = g_parent[i]) != i) i = p;
    return i;
}

__device__ __forceinline__ void unite(int a, int b) {
    int ra = find_ro(a);
    int rb = find_ro(b);
    while (ra != rb) {
        if (ra < rb) { int t = ra; ra = rb; rb = t; }  // ra > rb
        int old = atomicMin(&g_parent[ra], rb);
        if (old == ra) break;       // we linked ra -> rb
        // Someone else already linked ra -> old (old < ra). Now merge old & rb.
        ra = find_ro(old);
        rb = find_ro(rb);
    }
}

// ---------------------------------------------------------------------------
// K0: threshold + init scratch
// ---------------------------------------------------------------------------
__global__ void k_init(const float* __restrict__ x) {
    int i = blockIdx.x * blockDim.x + threadIdx.x;
    if (i >= Nn) return;
    g_parent[i] = (x[i] >= THRESH) ? i : -1;
    g_agg[i]    = 0ull;
    g_area[i]   = 0;
}

// ---------------------------------------------------------------------------
// K1: union with backward 8-neighbors (left, up-left, up, up-right),
// confined to the same batch image.
// ---------------------------------------------------------------------------
__global__ void k_merge() {
    int i = blockIdx.x * blockDim.x + threadIdx.x;
    if (i >= Nn) return;
    if (g_parent[i] < 0) return;            // background
    int c = i & (Wn - 1);
    int r = (i >> 10) & (Hn - 1);

    if (c > 0            && g_parent[i - 1]       >= 0) unite(i, i - 1);
    if (r > 0) {
        if (              g_parent[i - Wn]        >= 0) unite(i, i - Wn);
        if (c > 0      && g_parent[i - Wn - 1]    >= 0) unite(i, i - Wn - 1);
        if (c < Wn - 1 && g_parent[i - Wn + 1]    >= 0) unite(i, i - Wn + 1);
    }
}

// ---------------------------------------------------------------------------
// K2: path-compress + aggregate (area via atomicAdd; max value + min tie
// index via one packed 64-bit atomicMax). x >= 1.5 > 0 so float bits order
// as unsigned ints; ~within makes larger key == smaller within index.
// ---------------------------------------------------------------------------
__global__ void k_aggregate(const float* __restrict__ x) {
    int i = blockIdx.x * blockDim.x + threadIdx.x;
    if (i >= Nn) return;
    if (g_parent[i] < 0) return;
    int root = find_ro(i);
    g_parent[i] = root;                     // full compression (no unions now)
    atomicAdd(&g_area[root], 1);
    unsigned int vb     = (unsigned int)__float_as_int(x[i]);
    unsigned int within = (unsigned int)(i & (HW - 1));
    unsigned long long key = ((unsigned long long)vb << 32) |
                             (unsigned long long)(~within);
    atomicMax(&g_agg[root], key);
}

// ---------------------------------------------------------------------------
// K3: emit dense outputs (max, row, col) as float32, concatenated.
// ---------------------------------------------------------------------------
__global__ void k_emit(float* __restrict__ out, int write_rc) {
    int i = blockIdx.x * blockDim.x + threadIdx.x;
    if (i >= Nn) return;
    int p = g_parent[i];
    float maxv = 0.0f;
    float rowf = -1.0f, colf = -1.0f;
    if (p >= 0 && g_area[p] > MIN_AREA_C) {
        unsigned long long k = g_agg[p];
        maxv = __int_as_float((int)(unsigned int)(k >> 32));
        unsigned int within = ~(unsigned int)(k & 0xFFFFFFFFull);
        rowf = (float)(within >> 10);        // within / W
        colf = (float)(within & (Wn - 1));   // within % W
    }
    out[i] = maxv;
    if (write_rc) {
        out[Nn + i]     = rowf;
        out[2 * Nn + i] = colf;
    }
}

extern "C" void kernel_launch(void* const* d_in, const int* in_sizes, int n_in,
                              void* d_out, int out_size) {
    const float* x = (const float*)d_in[0];
    float* out = (float*)d_out;
    const int threads = 256;
    const int blocks  = (Nn + threads - 1) / threads;
    int write_rc = (out_size >= 3 * Nn) ? 1 : 0;

    k_init<<<blocks, threads>>>(x);
    k_merge<<<blocks, threads>>>();
    k_aggregate<<<blocks, threads>>>(x);
    k_emit<<<blocks, threads>>>(out, write_rc);
}

// round 3
// speedup vs baseline: 1.5811x; 1.5811x over previous
#include <cuda_runtime.h>
#include <stdint.h>

#define Bn 8
#define Hn 1024
#define Wn 1024
#define HW (Hn * Wn)
#define Nn (Bn * Hn * Wn)
#define THRESH 1.5f
#define MIN_AREA_C 3
#define TPB 256
#define PPT 4                      // pixels per thread (vector width)
#define NTHREADTOT (Nn / PPT)

// Scratch in __device__ globals (no runtime allocation allowed).
__device__ int                g_parent[Nn];   // fg: union-find parent; bg: -1
__device__ unsigned long long g_agg[Nn];      // per-root packed (val_bits<<32) | ~within
__device__ int                g_area[Nn];     // per-root pixel count

// ---------------------------------------------------------------------------
// Union-find. Roots only decrease (atomicMin links high -> low), so read-only
// find is race-safe during merge.
// ---------------------------------------------------------------------------
__device__ __forceinline__ int find_ro(int i) {
    int p;
    while ((p = g_parent[i]) != i) i = p;
    return i;
}

__device__ __forceinline__ void unite(int a, int b) {
    int ra = find_ro(a);
    int rb = find_ro(b);
    while (ra != rb) {
        if (ra < rb) { int t = ra; ra = rb; rb = t; }  // ra > rb
        int old = atomicMin(&g_parent[ra], rb);
        if (old == ra) break;
        ra = find_ro(old);
        rb = find_ro(rb);
    }
}

// ---------------------------------------------------------------------------
// K0: threshold + init. Only fg entries of agg/area are ever read (roots are
// fg pixels), so init them conditionally.
// ---------------------------------------------------------------------------
__global__ void k_init(const float* __restrict__ x) {
    int t = blockIdx.x * blockDim.x + threadIdx.x;
    if (t >= NTHREADTOT) return;
    int base = t * PPT;
    float4 v = *reinterpret_cast<const float4*>(x + base);
    int4 p;
    p.x = (v.x >= THRESH) ? base     : -1;
    p.y = (v.y >= THRESH) ? base + 1 : -1;
    p.z = (v.z >= THRESH) ? base + 2 : -1;
    p.w = (v.w >= THRESH) ? base + 3 : -1;
    *reinterpret_cast<int4*>(g_parent + base) = p;
    if (p.x >= 0) { g_agg[base]     = 0ull; g_area[base]     = 0; }
    if (p.y >= 0) { g_agg[base + 1] = 0ull; g_area[base + 1] = 0; }
    if (p.z >= 0) { g_agg[base + 2] = 0ull; g_area[base + 2] = 0; }
    if (p.w >= 0) { g_agg[base + 3] = 0ull; g_area[base + 3] = 0; }
}

// ---------------------------------------------------------------------------
// K1: union with backward 8-neighbors. 4 px/thread: one int4 covers this run,
// one int4 covers the row above; left neighbor comes from the register chain.
// Komura pruning: if 'up' is fg, skip up-left/up-right (already connected
// through up via row-wise left unions).
// ---------------------------------------------------------------------------
__global__ void k_merge() {
    int t = blockIdx.x * blockDim.x + threadIdx.x;
    if (t >= NTHREADTOT) return;
    int base = t * PPT;
    int c0 = base & (Wn - 1);
    int r  = (base >> 10) & (Hn - 1);

    int4 pc = *reinterpret_cast<const int4*>(g_parent + base);
    int fgc[PPT] = { pc.x >= 0, pc.y >= 0, pc.z >= 0, pc.w >= 0 };
    if (!(fgc[0] | fgc[1] | fgc[2] | fgc[3])) return;

    int up[PPT + 2];   // up[k] = parent[base - Wn + (k-1)], k=0..5
    if (r > 0) {
        int4 pu = *reinterpret_cast<const int4*>(g_parent + base - Wn);
        up[1] = pu.x; up[2] = pu.y; up[3] = pu.z; up[4] = pu.w;
        up[0] = (c0 > 0)        ? g_parent[base - Wn - 1]  : -1;
        up[5] = (c0 < Wn - PPT) ? g_parent[base - Wn + 4]  : -1;
    } else {
        up[0] = up[1] = up[2] = up[3] = up[4] = up[5] = -1;
    }
    int pl = (c0 > 0) ? g_parent[base - 1] : -1;
    int lf[PPT] = { pl >= 0, fgc[0], fgc[1], fgc[2] };

    #pragma unroll
    for (int k = 0; k < PPT; k++) {
        if (!fgc[k]) continue;
        int i = base + k;
        if (lf[k]) unite(i, i - 1);
        if (up[k + 1] >= 0) {
            unite(i, i - Wn);
        } else {
            if (up[k] >= 0)     unite(i, i - Wn - 1);
            if (up[k + 2] >= 0) unite(i, i - Wn + 1);
        }
    }
}

// ---------------------------------------------------------------------------
// K2: path-compress + aggregate. Packed 64-bit atomicMax fuses max value and
// min-index-of-max (positive float bits order as uint; ~within flips order).
// ---------------------------------------------------------------------------
__global__ void k_aggregate(const float* __restrict__ x) {
    int t = blockIdx.x * blockDim.x + threadIdx.x;
    if (t >= NTHREADTOT) return;
    int base = t * PPT;
    int4 pc = *reinterpret_cast<const int4*>(g_parent + base);
    int pv[PPT] = { pc.x, pc.y, pc.z, pc.w };
    if ((pv[0] | pv[1] | pv[2] | pv[3]) < 0 &&
        pv[0] < 0 && pv[1] < 0 && pv[2] < 0 && pv[3] < 0) return;
    float4 v = *reinterpret_cast<const float4*>(x + base);
    float vv[PPT] = { v.x, v.y, v.z, v.w };

    int roots[PPT];
    #pragma unroll
    for (int k = 0; k < PPT; k++)
        roots[k] = (pv[k] >= 0) ? find_ro(base + k) : -1;

    #pragma unroll
    for (int k = 0; k < PPT; k++) {
        if (roots[k] < 0) continue;
        int i = base + k;
        atomicAdd(&g_area[roots[k]], 1);
        unsigned int vb     = (unsigned int)__float_as_int(vv[k]);
        unsigned int within = (unsigned int)(i & (HW - 1));
        unsigned long long key = ((unsigned long long)vb << 32) |
                                 (unsigned long long)(~within);
        atomicMax(&g_agg[roots[k]], key);
    }
    // full path compression for the emit pass (each thread owns its 4 slots)
    pc.x = roots[0] >= 0 ? roots[0] : -1;
    pc.y = roots[1] >= 0 ? roots[1] : -1;
    pc.z = roots[2] >= 0 ? roots[2] : -1;
    pc.w = roots[3] >= 0 ? roots[3] : -1;
    *reinterpret_cast<int4*>(g_parent + base) = pc;
}

// ---------------------------------------------------------------------------
// K3: emit dense (max, row, col) float32 outputs, 4 px/thread, float4 stores.
// ---------------------------------------------------------------------------
__global__ void k_emit(float* __restrict__ out, int write_rc) {
    int t = blockIdx.x * blockDim.x + threadIdx.x;
    if (t >= NTHREADTOT) return;
    int base = t * PPT;
    int4 pc = *reinterpret_cast<const int4*>(g_parent + base);
    int pv[PPT] = { pc.x, pc.y, pc.z, pc.w };

    float mx[PPT], rw[PPT], cl[PPT];
    // issue independent gathers first for MLP
    int ar[PPT];
    #pragma unroll
    for (int k = 0; k < PPT; k++)
        ar[k] = (pv[k] >= 0) ? __ldg(&g_area[pv[k]]) : 0;

    #pragma unroll
    for (int k = 0; k < PPT; k++) {
        mx[k] = 0.0f; rw[k] = -1.0f; cl[k] = -1.0f;
        if (pv[k] >= 0 && ar[k] > MIN_AREA_C) {
            unsigned long long key = __ldg(&g_agg[pv[k]]);
            mx[k] = __int_as_float((int)(unsigned int)(key >> 32));
            unsigned int within = ~(unsigned int)(key & 0xFFFFFFFFull);
            rw[k] = (float)(within >> 10);
            cl[k] = (float)(within & (Wn - 1));
        }
    }
    *reinterpret_cast<float4*>(out + base) = make_float4(mx[0], mx[1], mx[2], mx[3]);
    if (write_rc) {
        *reinterpret_cast<float4*>(out + Nn + base)     = make_float4(rw[0], rw[1], rw[2], rw[3]);
        *reinterpret_cast<float4*>(out + 2 * Nn + base) = make_float4(cl[0], cl[1], cl[2], cl[3]);
    }
}

extern "C" void kernel_launch(void* const* d_in, const int* in_sizes, int n_in,
                              void* d_out, int out_size) {
    const float* x = (const float*)d_in[0];
    float* out = (float*)d_out;
    const int blocks = (NTHREADTOT + TPB - 1) / TPB;
    int write_rc = (out_size >= 3 * Nn) ? 1 : 0;

    k_init<<<blocks, TPB>>>(x);
    k_merge<<<blocks, TPB>>>();
    k_aggregate<<<blocks, TPB>>>(x);
    k_emit<<<blocks, TPB>>>(out, write_rc);
}